// round 10
// baseline (speedup 1.0000x reference)
#include <cuda_runtime.h>

// Scratch: __device__ globals only (no allocation allowed).
#define MAXV (1 << 19)      // 512k vertices (actual V ~ 185k)
#define KMAX 16             // adjacency storage slots per vertex
#define KUNROLL 8           // fast path covers valence <= 8

// Windowed-gather geometry
#define VPB  1024           // vertices per gather block
#define TG   512            // threads per gather block (2 verts/thread)
#define HALO 2048           // window halo each side (index units)
#define WIN  (VPB + 2 * HALO)   // 5120 float4 = 80 KB smem

__device__ float4 g_x[MAXV];            // positions (iter-1 input)
__device__ float4 g_y[MAXV];            // positions after iter 1
__device__ int    g_cnt[MAXV];          // degree / slot counter
__device__ int    g_adj[KMAX * MAXV];   // slot-major adjacency (coalesced over v)

// ---------------------------------------------------------------------------
// Fused: pack v -> g_x + zero counters (first gV blocks); faces int->float
// copy (remaining blocks, int4-vectorized).
__global__ void k_repack_faces(const float* __restrict__ v, int V, int gV,
                               const int* __restrict__ faces,
                               float* __restrict__ fout, int nF3) {
    if ((int)blockIdx.x < gV) {
        int i = blockIdx.x * blockDim.x + threadIdx.x;
        if (i < V) {
            g_x[i] = make_float4(v[3 * i], v[3 * i + 1], v[3 * i + 2], 0.f);
            g_cnt[i] = 0;
        }
    } else {
        int t = (blockIdx.x - gV) * blockDim.x + threadIdx.x;
        int base = t * 4;
        if (base + 4 <= nF3) {
            int4 f = *(const int4*)(faces + base);
            *(float4*)(fout + base) =
                make_float4((float)f.x, (float)f.y, (float)f.z, (float)f.w);
        } else if (base < nF3) {
            for (int j = base; j < nF3; ++j) fout[j] = (float)faces[j];
        }
    }
}

// Build adjacency: each edge registers itself at both endpoints.
__global__ void k_fill(const int2* __restrict__ edges, int E) {
    int i = blockIdx.x * blockDim.x + threadIdx.x;
    if (i < E) {
        int2 e = edges[i];
        int sa = atomicAdd(&g_cnt[e.x], 1) & (KMAX - 1);
        int sb = atomicAdd(&g_cnt[e.y], 1) & (KMAX - 1);
        g_adj[sa * MAXV + e.x] = e.y;
        g_adj[sb * MAXV + e.y] = e.x;
    }
}

// Windowed gather: block stages a contiguous position window in smem
// (coalesced), then resolves neighbors from smem; global fallback for
// out-of-window neighbors keeps correctness data-independent.
template <bool FINAL>
__global__ __launch_bounds__(TG) void k_gather_win(float* __restrict__ out, int V) {
    extern __shared__ float4 win[];
    const float4* __restrict__ src = FINAL ? g_y : g_x;

    const int base  = (int)blockIdx.x * VPB;
    const int wbase = base - HALO;

    // Stage window (clamped at array ends; clamped entries are broadcasts).
#pragma unroll 2
    for (int i = threadIdx.x; i < WIN; i += TG) {
        int idx = wbase + i;
        idx = idx < 0 ? 0 : (idx >= V ? V - 1 : idx);
        win[i] = src[idx];
    }
    __syncthreads();

#pragma unroll
    for (int r = 0; r < VPB / TG; ++r) {
        int v = base + r * TG + threadIdx.x;
        if (v >= V) continue;
        int d = g_cnt[v];
        if (d > KMAX) d = KMAX;

        // Coalesced adjacency (slot-major), unconditional front batch.
        int nb[KUNROLL];
#pragma unroll
        for (int j = 0; j < KUNROLL; ++j)
            nb[j] = g_adj[j * MAXV + v];

        float sx = 0.f, sy = 0.f, sz = 0.f;
#pragma unroll
        for (int j = 0; j < KUNROLL; ++j) {
            if (j < d) {
                int rel = nb[j] - wbase;
                float4 p = (rel >= 0 && rel < WIN) ? win[rel]
                                                   : __ldg(&src[nb[j]]);
                sx += p.x; sy += p.y; sz += p.z;
            }
        }
        for (int j = KUNROLL; j < d; ++j) {
            float4 p = __ldg(&src[g_adj[j * MAXV + v]]);
            sx += p.x; sy += p.y; sz += p.z;
        }

        float inv = 1.0f / fmaxf((float)d, 1.0f);
        if (FINAL) {
            out[3 * v + 0] = sx * inv;
            out[3 * v + 1] = sy * inv;
            out[3 * v + 2] = sz * inv;
        } else {
            g_y[v] = make_float4(sx * inv, sy * inv, sz * inv, 0.f);
        }
    }
}

// ---------------------------------------------------------------------------
extern "C" void kernel_launch(void* const* d_in, const int* in_sizes, int n_in,
                              void* d_out, int out_size) {
    const float* v     = (const float*)d_in[0];   // [1,V,3] f32
    const int2*  edges = (const int2*)d_in[1];    // [E,2]   i32
    const int*   faces = (const int*)d_in[2];     // [1,F,3] i32

    const int V   = in_sizes[0] / 3;
    const int E   = in_sizes[1] / 2;
    const int nF3 = in_sizes[2];

    float* out  = (float*)d_out;
    float* fout = out + 3 * V;
    const bool do_faces = (out_size >= 3 * V + nF3);

    const int T = 256;
    const int gV = (V + T - 1) / T;
    const int gE = (E + T - 1) / T;
    const int gF = do_faces ? ((nF3 + 4 * T - 1) / (4 * T)) : 0;
    const int gW = (V + VPB - 1) / VPB;
    const int smem = WIN * sizeof(float4);   // 80 KB dynamic smem

    // Opt in to >48KB dynamic smem (idempotent; not a stream op).
    static bool attr_done = false;
    if (!attr_done) {
        cudaFuncSetAttribute(k_gather_win<false>,
                             cudaFuncAttributeMaxDynamicSharedMemorySize, smem);
        cudaFuncSetAttribute(k_gather_win<true>,
                             cudaFuncAttributeMaxDynamicSharedMemorySize, smem);
        attr_done = true;
    }

    k_repack_faces<<<gV + gF, T>>>(v, V, gV, faces, fout, do_faces ? nF3 : 0);
    k_fill<<<gE, T>>>(edges, E);
    k_gather_win<false><<<gW, TG, smem>>>(nullptr, V);   // iter 1: g_x -> g_y
    k_gather_win<true><<<gW, TG, smem>>>(out, V);        // iter 2: g_y -> out
}